// round 13
// baseline (speedup 1.0000x reference)
#include <cuda_runtime.h>
#include <cuda_fp16.h>
#include <mma.h>
#include <math.h>

using namespace nvcuda;

// Problem constants
#define BB    4
#define NN    2048
#define DD    256
#define HH    4
#define DHH   64
#define BH    16
#define MTOT  8192
#define QKSCALE 0.35355339059327379f  // 64^{-0.25}

// -------- scratch ----------
__device__ __half g_xh [2][MTOT * DD];
__device__ __half g_wqk[DD * DD];
__device__ __half g_wv [DD * DD];
__device__ __half g_wout[DD * DD];
__device__ __half g_wf1[4 * DD * DD];         // 512x512
__device__ __half g_wf2[2 * DD * DD];         // 512x256
__device__ __half g_wcomb[DD * 2 * DD];       // w_out @ w_f1[256:,:]  (256x512)
__device__ float  g_bcomb[2 * DD];            // b_f1 + b_out @ w_f1[256:,:]
__device__ __half g_qk [2][BH * NN * DHH];
__device__ __half g_v  [2][BH * NN * DHH];
__device__ __half g_att[2][MTOT * DD];
__device__ float  g_h  [2][MTOT * 2 * DD];
__device__ __half g_hh [2][MTOT * 2 * DD];

using FragAh  = wmma::fragment<wmma::matrix_a, 16, 16, 16, __half, wmma::row_major>;
using FragBh  = wmma::fragment<wmma::matrix_b, 16, 16, 16, __half, wmma::row_major>;
using FragC16 = wmma::fragment<wmma::accumulator, 16, 16, 16, float>;

// ---- cp.async ----
__device__ __forceinline__ void cp16(void* smem_dst, const void* gsrc) {
    unsigned int s = (unsigned int)__cvta_generic_to_shared(smem_dst);
    asm volatile("cp.async.cg.shared.global [%0], [%1], 16;" :: "r"(s), "l"(gsrc));
}
#define CP_COMMIT() asm volatile("cp.async.commit_group;")
#define CP_WAIT0()  asm volatile("cp.async.wait_group 0;")

// ---- ldmatrix / mma ----
__device__ __forceinline__ unsigned smem_u32(const void* p) {
    return (unsigned)__cvta_generic_to_shared(p);
}
__device__ __forceinline__ void ldm_x4(unsigned& r0, unsigned& r1,
                                       unsigned& r2, unsigned& r3, unsigned a) {
    asm volatile("ldmatrix.sync.aligned.m8n8.x4.shared.b16 {%0,%1,%2,%3}, [%4];"
                 : "=r"(r0), "=r"(r1), "=r"(r2), "=r"(r3) : "r"(a));
}
__device__ __forceinline__ void ldm_x4_t(unsigned& r0, unsigned& r1,
                                         unsigned& r2, unsigned& r3, unsigned a) {
    asm volatile("ldmatrix.sync.aligned.m8n8.x4.trans.shared.b16 {%0,%1,%2,%3}, [%4];"
                 : "=r"(r0), "=r"(r1), "=r"(r2), "=r"(r3) : "r"(a));
}
__device__ __forceinline__ void mma_f16(float d[4], const unsigned a[4],
                                        unsigned b0, unsigned b1) {
    asm volatile(
        "mma.sync.aligned.m16n8k16.row.col.f32.f16.f16.f32 "
        "{%0,%1,%2,%3}, {%4,%5,%6,%7}, {%8,%9}, {%0,%1,%2,%3};"
        : "+f"(d[0]), "+f"(d[1]), "+f"(d[2]), "+f"(d[3])
        : "r"(a[0]), "r"(a[1]), "r"(a[2]), "r"(a[3]), "r"(b0), "r"(b1));
}
__device__ __forceinline__ unsigned packh2(float lo, float hi) {
    __half2 h = __floats2half2_rn(lo, hi);
    return *reinterpret_cast<unsigned*>(&h);
}

// ==========================================================================
// Kernel 0: f32 -> f16 conversion (inputs + weights)
// ==========================================================================
__global__ __launch_bounds__(256) void cvt_kernel(
    const float* __restrict__ x0, const float* __restrict__ x1,
    const float* __restrict__ wqk, const float* __restrict__ wv,
    const float* __restrict__ wout, const float* __restrict__ wf1,
    const float* __restrict__ wf2)
{
    const float* src; __half* dst; int n;
    switch (blockIdx.y) {
    case 0: src = x0;  dst = g_xh[0]; n = MTOT * DD;  break;
    case 1: src = x1;  dst = g_xh[1]; n = MTOT * DD;  break;
    case 2: src = wqk; dst = g_wqk;   n = DD * DD;    break;
    case 3: src = wv;  dst = g_wv;    n = DD * DD;    break;
    case 4: src = wout;dst = g_wout;  n = DD * DD;    break;
    case 5: src = wf1; dst = g_wf1;   n = 4 * DD * DD;break;
    default:src = wf2; dst = g_wf2;   n = 2 * DD * DD;break;
    }
    int idx = (blockIdx.x * 256 + threadIdx.x) * 4;
    if (idx < n) {
        float4 v = *(const float4*)(src + idx);
        *(__half2*)(dst + idx)     = __floats2half2_rn(v.x, v.y);
        *(__half2*)(dst + idx + 2) = __floats2half2_rn(v.z, v.w);
    }
}

// ==========================================================================
// Kernel 0b: b_comb = b_f1 + b_out @ w_f1[256:,:]   grid 4 x 128
// ==========================================================================
__global__ __launch_bounds__(128) void bcomb_kernel(
    const float* __restrict__ b_out, const float* __restrict__ w_f1,
    const float* __restrict__ b_f1)
{
    int c = blockIdx.x * 128 + threadIdx.x;
    float s = b_f1[c];
#pragma unroll 8
    for (int k = 0; k < 256; k++)
        s += b_out[k] * w_f1[(size_t)(256 + k) * 512 + c];
    g_bcomb[c] = s;
}

// ==========================================================================
// FP16 GEMM block: BM=128, BN=128, BK=32, 8 warps (2x4), warp tile 64x32.
// ==========================================================================
#define ASH_LD 40
#define BSH_LD 136
#define ST_LD  20

__device__ __forceinline__ void gemm_core_h(const __half* As, const __half* Bs,
                                            FragC16 acc[4][2], int wr, int wc)
{
#pragma unroll
    for (int kk = 0; kk < 2; kk++) {
        FragAh af[4];
        FragBh bf[2];
#pragma unroll
        for (int i = 0; i < 4; i++)
            wmma::load_matrix_sync(af[i], As + (wr * 64 + i * 16) * ASH_LD + kk * 16, ASH_LD);
#pragma unroll
        for (int j = 0; j < 2; j++)
            wmma::load_matrix_sync(bf[j], Bs + (kk * 16) * BSH_LD + wc * 32 + j * 16, BSH_LD);
#pragma unroll
        for (int i = 0; i < 4; i++)
#pragma unroll
            for (int j = 0; j < 2; j++)
                wmma::mma_sync(acc[i][j], af[i], bf[j], acc[i][j]);
    }
}

__device__ __forceinline__ void issue_Ah(__half* As, const __half* A, int mBase,
                                         int kt, int lda, int tid)
{
#pragma unroll
    for (int it = 0; it < 2; it++) {
        int i = tid + it * 256;
        int row = i >> 2, c8 = i & 3;
        cp16(As + row * ASH_LD + c8 * 8,
             A + (size_t)(mBase + row) * lda + kt + c8 * 8);
    }
}
__device__ __forceinline__ void issue_Bh(__half* Bs, const __half* B, int kt,
                                         int cOff, int ldb, int tid)
{
#pragma unroll
    for (int it = 0; it < 2; it++) {
        int i = tid + it * 256;
        int k = i >> 4, c8 = i & 15;
        cp16(Bs + k * BSH_LD + c8 * 8,
             B + (size_t)(kt + k) * ldb + cOff + c8 * 8);
    }
}

// ==========================================================================
// Kernel 0c: w_comb = w_out @ w_f1[256:,:]  (256x512, fp16). grid (4, 2)
// ==========================================================================
__global__ __launch_bounds__(256) void wcomb_kernel()
{
    __shared__ __align__(16) __half As[2][128 * ASH_LD];
    __shared__ __align__(16) __half Bs[2][32 * BSH_LD];

    const __half* A = g_wout;
    const __half* B = g_wf1 + 256 * 512;
    const int mBase = blockIdx.y * 128;
    const int cBase = blockIdx.x * 128;
    const int tid = threadIdx.x;
    const int warp = tid >> 5, lane = tid & 31;
    const int wr = warp >> 2, wc = warp & 3;

    FragC16 acc[4][2];
#pragma unroll
    for (int i = 0; i < 4; i++)
#pragma unroll
        for (int j = 0; j < 2; j++) wmma::fill_fragment(acc[i][j], 0.f);

    issue_Ah(As[0], A, mBase, 0, DD, tid);
    issue_Bh(Bs[0], B, 0, cBase, 512, tid);
    CP_COMMIT();
    int buf = 0;
    for (int kt = 0; kt < 256; kt += 32) {
        CP_WAIT0();
        __syncthreads();
        if (kt + 32 < 256) {
            issue_Ah(As[buf ^ 1], A, mBase, kt + 32, DD, tid);
            issue_Bh(Bs[buf ^ 1], B, kt + 32, cBase, 512, tid);
            CP_COMMIT();
        }
        gemm_core_h(As[buf], Bs[buf], acc, wr, wc);
        buf ^= 1;
    }
    __syncthreads();

    float* stg = (float*)As + warp * (16 * ST_LD);
    const int r = lane >> 1, c0 = (lane & 1) * 8;
#pragma unroll
    for (int i = 0; i < 4; i++)
#pragma unroll
        for (int j = 0; j < 2; j++) {
            wmma::store_matrix_sync(stg, acc[i][j], ST_LD, wmma::mem_row_major);
            __syncwarp();
            int gm = mBase + wr * 64 + i * 16 + r;
            int gc = cBase + wc * 32 + j * 16 + c0;
            const float* sp = stg + r * ST_LD + c0;
            __half* dst = g_wcomb + (size_t)gm * 512 + gc;
#pragma unroll
            for (int u = 0; u < 8; u += 2)
                *(__half2*)(dst + u) = __floats2half2_rn(sp[u], sp[u + 1]);
            __syncwarp();
        }
}

// ==========================================================================
// Kernel 1: fused QK/V projection. grid (4, 64, 2)
// ==========================================================================
__global__ __launch_bounds__(256) void qkv_kernel(
    const float* __restrict__ b_qk, const float* __restrict__ b_v)
{
    __shared__ __align__(16) __half As[2][128 * ASH_LD];
    __shared__ __align__(16) __half Bs[2][32 * BSH_LD];

    const int s = blockIdx.z;
    const __half* A = g_xh[s];
    const int mBase = blockIdx.y * 128;
    const int cBase = blockIdx.x * 128;
    const int tid = threadIdx.x;
    const int warp = tid >> 5, lane = tid & 31;
    const int wr = warp >> 2, wc = warp & 3;

    const __half* W; int cOff;
    if (cBase < 256) { W = g_wqk; cOff = cBase; }
    else             { W = g_wv;  cOff = cBase - 256; }

    FragC16 acc[4][2];
#pragma unroll
    for (int i = 0; i < 4; i++)
#pragma unroll
        for (int j = 0; j < 2; j++) wmma::fill_fragment(acc[i][j], 0.f);

    issue_Ah(As[0], A, mBase, 0, DD, tid);
    issue_Bh(Bs[0], W, 0, cOff, DD, tid);
    CP_COMMIT();
    int buf = 0;
    for (int kt = 0; kt < 256; kt += 32) {
        CP_WAIT0();
        __syncthreads();
        if (kt + 32 < 256) {
            issue_Ah(As[buf ^ 1], A, mBase, kt + 32, DD, tid);
            issue_Bh(Bs[buf ^ 1], W, kt + 32, cOff, DD, tid);
            CP_COMMIT();
        }
        gemm_core_h(As[buf], Bs[buf], acc, wr, wc);
        buf ^= 1;
    }
    __syncthreads();

    float* stg = (float*)As + warp * (16 * ST_LD);
    const int r = lane >> 1, c0 = (lane & 1) * 8;
#pragma unroll
    for (int i = 0; i < 4; i++)
#pragma unroll
        for (int j = 0; j < 2; j++) {
            wmma::store_matrix_sync(stg, acc[i][j], ST_LD, wmma::mem_row_major);
            __syncwarp();
            int gm = mBase + wr * 64 + i * 16 + r;
            int gc = cBase + wc * 32 + j * 16 + c0;
            int b = gm >> 11, n = gm & 2047;
#pragma unroll
            for (int u = 0; u < 8; u++) {
                float v = stg[r * ST_LD + c0 + u];
                int c = gc + u;
                if (c < 256) {
                    int h = c >> 6, d = c & 63;
                    g_qk[s][(((size_t)(b * HH + h) * NN + n) * DHH) + d] =
                        __float2half_rn((v + b_qk[c]) * QKSCALE);
                } else {
                    int c2 = c - 256;
                    int h = c2 >> 6, d = c2 & 63;
                    g_v[s][(((size_t)(b * HH + h) * NN + n) * DHH) + d] =
                        __float2half_rn(v + b_v[c2]);
                }
            }
            __syncwarp();
        }
}

// ==========================================================================
// Kernel 2: attention — raw mma m16n8k16, register-resident softmax
// (FlashAttention-2 S->P register reuse; no smem roundtrip, no syncwarp).
// grid (16, 16, 2) block 256. smem: Ks2[2][64x72] Vs2[2][64x72] Ph[128x72]
// ==========================================================================
#define KV_LD 72
#define PH_LD 72
#define ATTN_SMEM (18432 * 3)

__global__ __launch_bounds__(256) void attn_kernel()
{
    extern __shared__ char smc[];
    __half* Ks2 = (__half*)smc;
    __half* Vs2 = (__half*)(smc + 18432);
    __half* Ph  = (__half*)(smc + 36864);

    const int s  = blockIdx.z;
    const int bh = blockIdx.y;
    const int qb = blockIdx.x;
    const __half* Q = g_qk[s]     + (size_t)bh * NN * DHH + (size_t)qb * 128 * DHH;
    const __half* K = g_qk[s ^ 1] + (size_t)bh * NN * DHH;
    const __half* V = g_v [s ^ 1] + (size_t)bh * NN * DHH;

    const int tid = threadIdx.x;
    const int w = tid >> 5;
    const int lane = tid & 31;
    const int g = lane >> 2, qc = lane & 3;

    // stage Q (128x64 halves)
#pragma unroll
    for (int it = 0; it < 4; it++) {
        int i = tid + it * 256;
        int r = i >> 3, c8 = i & 7;
        cp16(Ph + r * PH_LD + c8 * 8, Q + r * 64 + c8 * 8);
    }
    // KV block 0
#pragma unroll
    for (int it = 0; it < 2; it++) {
        int i = tid + it * 256;
        int r = i >> 3, c8 = i & 7;
        cp16(Ks2 + r * KV_LD + c8 * 8, K + r * 64 + c8 * 8);
        cp16(Vs2 + r * KV_LD + c8 * 8, V + r * 64 + c8 * 8);
    }
    CP_COMMIT();
    CP_WAIT0();
    __syncthreads();

    // preload Q A-fragments: 4 k-chunks of 16
    unsigned qA[4][4];
    {
        int row = (w << 4) + (lane & 7) + (((lane >> 3) & 1) << 3);
        int ch  = ((lane >> 4) & 1) << 3;
#pragma unroll
        for (int kk = 0; kk < 4; kk++) {
            unsigned ad = smem_u32(Ph + row * PH_LD + kk * 16 + ch);
            ldm_x4(qA[kk][0], qA[kk][1], qA[kk][2], qA[kk][3], ad);
        }
    }

    float o[8][4];
#pragma unroll
    for (int j = 0; j < 8; j++)
#pragma unroll
        for (int t = 0; t < 4; t++) o[j][t] = 0.f;
    float lsum_lo = 0.f, lsum_hi = 0.f;
    int buf = 0;

    // per-lane ldmatrix address components
    const int k_nrow_off = (lane & 7) + (((lane >> 4) & 1) << 3);   // K: n-row
    const int k_col_off  = (((lane >> 3) & 1) << 3);                // K: k-col
    const int v_krow_off = (lane & 7) + (((lane >> 3) & 1) << 3);   // V: k-row
    const int v_col_off  = (((lane >> 4) & 1) << 3);                // V: n-col

    for (int kb = 0; kb < NN / 64; kb++) {
        CP_WAIT0();
        __syncthreads();
        if (kb + 1 < NN / 64) {
            const __half* Kb = K + (size_t)(kb + 1) * 64 * 64;
            const __half* Vb = V + (size_t)(kb + 1) * 64 * 64;
            __half* Kd = Ks2 + (buf ^ 1) * 64 * KV_LD;
            __half* Vd = Vs2 + (buf ^ 1) * 64 * KV_LD;
#pragma unroll
            for (int it = 0; it < 2; it++) {
                int i = tid + it * 256;
                int r = i >> 3, c8 = i & 7;
                cp16(Kd + r * KV_LD + c8 * 8, Kb + r * 64 + c8 * 8);
                cp16(Vd + r * KV_LD + c8 * 8, Vb + r * 64 + c8 * 8);
            }
            CP_COMMIT();
        }
        const __half* Ksb = Ks2 + buf * 64 * KV_LD;
        const __half* Vsb = Vs2 + buf * 64 * KV_LD;

        // S = Q @ K^T  (16 x 64 per warp), f32 accum in registers
        float sa[8][4];
#pragma unroll
        for (int j = 0; j < 8; j++)
#pragma unroll
            for (int t = 0; t < 4; t++) sa[j][t] = 0.f;
#pragma unroll
        for (int kk = 0; kk < 4; kk++) {
#pragma unroll
            for (int jp = 0; jp < 4; jp++) {
                unsigned b0, b1, b2, b3;
                unsigned ad = smem_u32(Ksb + (jp * 16 + k_nrow_off) * KV_LD
                                       + kk * 16 + k_col_off);
                ldm_x4(b0, b1, b2, b3, ad);
                mma_f16(sa[2 * jp],     qA[kk], b0, b1);
                mma_f16(sa[2 * jp + 1], qA[kk], b2, b3);
            }
        }

        // exp in registers; convert to P A-fragments; row sums via quad shfl
        unsigned pA[4][4];
        float rs_lo = 0.f, rs_hi = 0.f;
#pragma unroll
        for (int j = 0; j < 8; j++) {
            float e0 = __expf(sa[j][0]);
            float e1 = __expf(sa[j][1]);
            float e2 = __expf(sa[j][2]);
            float e3 = __expf(sa[j][3]);
            rs_lo += e0 + e1;
            rs_hi += e2 + e3;
            int kk = j >> 1, hi = (j & 1) << 1;
            pA[kk][hi]     = packh2(e0, e1);
            pA[kk][hi + 1] = packh2(e2, e3);
        }
        rs_lo += __shfl_xor_sync(0xffffffffu, rs_lo, 1);
        rs_lo += __shfl_xor_sync(0xffffffffu, rs_lo, 2);
        rs_hi += __shfl_xor_sync(0xffffffffu, rs_hi, 1);
        rs_hi += __shfl_xor_sync(0xffffffffu, rs_hi, 2);
        lsum_lo += rs_lo;
        lsum_hi += rs_hi;

        // O += P @ V
#pragma unroll
        for (int kk = 0; kk < 4; kk++) {
#pragma unroll
            for (int jp = 0; jp < 4; jp++) {
                unsigned b0, b1, b2, b3;
                unsigned ad = smem_u32(Vsb + (kk * 16 + v_krow_off) * KV_LD
                                       + jp * 16 + v_col_off);
                ldm_x4_t(b0, b1, b2, b3, ad);
                mma_f16(o[2 * jp],     pA[kk], b0, b1);
                mma_f16(o[2 * jp + 1], pA[kk], b2, b3);
            }
        }
        buf ^= 1;
    }

    // finalize: normalize in registers, write directly to gmem
    const int b = bh >> 2, h = bh & 3;
    const float il = 1.f / lsum_lo, ih = 1.f / lsum_hi;
    int n_lo = qb * 128 + w * 16 + g;
    __half* base_lo = g_att[s] + (size_t)(b * NN + n_lo) * DD + h * 64 + qc * 2;
    __half* base_hi = base_lo + (size_t)8 * DD;
#pragma unroll
    for (int j = 0; j < 8; j++) {
        *(__half2*)(base_lo + j * 8) = __floats2half2_rn(o[j][0] * il, o[j][1] * il);
        *(__half2*)(base_hi + j * 8) = __floats2half2_rn(o[j][2] * ih, o[j][3] * ih);
    }
}

// ==========================================================================
// Kernel 4: FFN1.  h = x @ w_f1_top + att @ w_comb + b_comb  (K=512)
// grid (4, 64, 2)
// ==========================================================================
__global__ __launch_bounds__(256) void ffn1_kernel()
{
    __shared__ __align__(16) __half As[2][128 * ASH_LD];
    __shared__ __align__(16) __half Bs[2][32 * BSH_LD];

    const int s = blockIdx.z;
    const __half* X  = g_xh[s];
    const __half* At = g_att[s];
    const int mBase = blockIdx.y * 128;
    const int cBase = blockIdx.x * 128;
    const int tid = threadIdx.x;
    const int warp = tid >> 5, lane = tid & 31;
    const int wr = warp >> 2, wc = warp & 3;

    FragC16 acc[4][2];
#pragma unroll
    for (int i = 0; i < 4; i++)
#pragma unroll
        for (int j = 0; j < 2; j++) wmma::fill_fragment(acc[i][j], 0.f);

    issue_Ah(As[0], X, mBase, 0, DD, tid);
    issue_Bh(Bs[0], g_wf1, 0, cBase, 512, tid);
    CP_COMMIT();
    int buf = 0;
    for (int kt = 0; kt < 512; kt += 32) {
        CP_WAIT0();
        __syncthreads();
        if (kt + 32 < 512) {
            int kn = kt + 32;
            const __half* Asrc = (kn < 256) ? X : At;
            int kOff = (kn < 256) ? kn : kn - 256;
            const __half* Bsrc = (kn < 256) ? g_wf1 : g_wcomb;
            int kB = (kn < 256) ? kn : kn - 256;
            issue_Ah(As[buf ^ 1], Asrc, mBase, kOff, DD, tid);
            issue_Bh(Bs[buf ^ 1], Bsrc, kB, cBase, 512, tid);
            CP_COMMIT();
        }
        gemm_core_h(As[buf], Bs[buf], acc, wr, wc);
        buf ^= 1;
    }
    __syncthreads();

    float* stg = (float*)As + warp * (16 * ST_LD);
    const int r = lane >> 1, c0 = (lane & 1) * 8;
#pragma unroll
    for (int i = 0; i < 4; i++)
#pragma unroll
        for (int j = 0; j < 2; j++) {
            wmma::store_matrix_sync(stg, acc[i][j], ST_LD, wmma::mem_row_major);
            __syncwarp();
            int gm = mBase + wr * 64 + i * 16 + r;
            int gc = cBase + wc * 32 + j * 16 + c0;
            float4 b0 = *(const float4*)(g_bcomb + gc);
            float4 b1 = *(const float4*)(g_bcomb + gc + 4);
            const float* sp = stg + r * ST_LD + c0;
            float4 v0 = make_float4(sp[0] + b0.x, sp[1] + b0.y, sp[2] + b0.z, sp[3] + b0.w);
            float4 v1 = make_float4(sp[4] + b1.x, sp[5] + b1.y, sp[6] + b1.z, sp[7] + b1.w);
            *(float4*)(&g_h[s][(size_t)gm * (2 * DD) + gc])     = v0;
            *(float4*)(&g_h[s][(size_t)gm * (2 * DD) + gc + 4]) = v1;
            __syncwarp();
        }
}

// ==========================================================================
// Kernel 5: LayerNorm(512) + exact GELU; f32 g_h -> half g_hh. grid 16384
// ==========================================================================
__global__ __launch_bounds__(128) void ln_gelu_kernel(
    const float* __restrict__ g, const float* __restrict__ bta)
{
    const int row = blockIdx.x;
    const int s = row >> 13;
    const int rr = row & 8191;
    const float* h = g_h[s] + (size_t)rr * 512;
    const int tid = threadIdx.x;

    float4 t = reinterpret_cast<const float4*>(h)[tid];
    float sum = t.x + t.y + t.z + t.w;
    float sq  = t.x * t.x + t.y * t.y + t.z * t.z + t.w * t.w;
#pragma unroll
    for (int off = 16; off > 0; off >>= 1) {
        sum += __shfl_xor_sync(0xffffffffu, sum, off);
        sq  += __shfl_xor_sync(0xffffffffu, sq,  off);
    }
    __shared__ float ssum[4], ssq[4];
    const int w = tid >> 5;
    if ((tid & 31) == 0) { ssum[w] = sum; ssq[w] = sq; }
    __syncthreads();
    sum = ssum[0] + ssum[1] + ssum[2] + ssum[3];
    sq  = ssq[0]  + ssq[1]  + ssq[2]  + ssq[3];

    const float mu   = sum * (1.f / 512.f);
    const float var  = sq * (1.f / 512.f) - mu * mu;
    const float rstd = rsqrtf(var + 1e-5f);

    float4 gg = reinterpret_cast<const float4*>(g)[tid];
    float4 bb = reinterpret_cast<const float4*>(bta)[tid];
    auto act = [&](float v, float gv, float bv) {
        float y = (v - mu) * rstd * gv + bv;
        return 0.5f * y * (1.f + erff(y * 0.70710678118654752f));
    };
    float r0 = act(t.x, gg.x, bb.x);
    float r1 = act(t.y, gg.y, bb.y);
    float r2 = act(t.z, gg.z, bb.z);
    float r3 = act(t.w, gg.w, bb.w);

    __half2* dst = (__half2*)(g_hh[s] + (size_t)rr * 512 + tid * 4);
    dst[0] = __floats2half2_rn(r0, r1);
    dst[1] = __floats2half2_rn(r2, r3);
}

// ==========================================================================
// Kernel 6: FFN2 + residual.  out = x + hh @ w_f2 + b_f2 (K=512). grid (2,64,2)
// ==========================================================================
__global__ __launch_bounds__(256) void ffn2_kernel(
    const float* __restrict__ x0, const float* __restrict__ x1,
    const float* __restrict__ bias, float* __restrict__ out)
{
    __shared__ __align__(16) __half As[2][128 * ASH_LD];
    __shared__ __align__(16) __half Bs[2][32 * BSH_LD];

    const int s = blockIdx.z;
    const float* X = s ? x1 : x0;
    const __half* A = g_hh[s];
    const int mBase = blockIdx.y * 128;
    const int cBase = blockIdx.x * 128;
    const int tid = threadIdx.x;
    const int warp = tid >> 5, lane = tid & 31;
    const int wr = warp >> 2, wc = warp & 3;

    FragC16 acc[4][2];
#pragma unroll
    for (int i = 0; i < 4; i++)
#pragma unroll
        for (int j = 0; j < 2; j++) wmma::fill_fragment(acc[i][j], 0.f);

    issue_Ah(As[0], A, mBase, 0, 2 * DD, tid);
    issue_Bh(Bs[0], g_wf2, 0, cBase, DD, tid);
    CP_COMMIT();
    int buf = 0;
    for (int kt = 0; kt < 512; kt += 32) {
        CP_WAIT0();
        __syncthreads();
        if (kt + 32 < 512) {
            issue_Ah(As[buf ^ 1], A, mBase, kt + 32, 2 * DD, tid);
            issue_Bh(Bs[buf ^ 1], g_wf2, kt + 32, cBase, DD, tid);
            CP_COMMIT();
        }
        gemm_core_h(As[buf], Bs[buf], acc, wr, wc);
        buf ^= 1;
    }
    __syncthreads();

    float* stg = (float*)As + warp * (16 * ST_LD);
    const int r = lane >> 1, c0 = (lane & 1) * 8;
#pragma unroll
    for (int i = 0; i < 4; i++)
#pragma unroll
        for (int j = 0; j < 2; j++) {
            wmma::store_matrix_sync(stg, acc[i][j], ST_LD, wmma::mem_row_major);
            __syncwarp();
            int gm = mBase + wr * 64 + i * 16 + r;
            int gc = cBase + wc * 32 + j * 16 + c0;
            float4 b0 = *(const float4*)(bias + gc);
            float4 b1 = *(const float4*)(bias + gc + 4);
            float4 x0v = *(const float4*)(X + (size_t)gm * DD + gc);
            float4 x1v = *(const float4*)(X + (size_t)gm * DD + gc + 4);
            const float* sp = stg + r * ST_LD + c0;
            float4 v0 = make_float4(sp[0] + b0.x + x0v.x, sp[1] + b0.y + x0v.y,
                                    sp[2] + b0.z + x0v.z, sp[3] + b0.w + x0v.w);
            float4 v1 = make_float4(sp[4] + b1.x + x1v.x, sp[5] + b1.y + x1v.y,
                                    sp[6] + b1.z + x1v.z, sp[7] + b1.w + x1v.w);
            *(float4*)(out + (size_t)s * MTOT * DD + (size_t)gm * DD + gc)     = v0;
            *(float4*)(out + (size_t)s * MTOT * DD + (size_t)gm * DD + gc + 4) = v1;
            __syncwarp();
        }
}

// ==========================================================================
extern "C" void kernel_launch(void* const* d_in, const int* in_sizes, int n_in,
                              void* d_out, int out_size)
{
    const float* x0    = (const float*)d_in[0];
    const float* x1    = (const float*)d_in[1];
    const float* w_qk  = (const float*)d_in[2];
    const float* b_qk  = (const float*)d_in[3];
    const float* w_v   = (const float*)d_in[4];
    const float* b_v   = (const float*)d_in[5];
    const float* w_out = (const float*)d_in[6];
    const float* b_out = (const float*)d_in[7];
    const float* w_f1  = (const float*)d_in[8];
    const float* b_f1  = (const float*)d_in[9];
    const float* ln_g  = (const float*)d_in[10];
    const float* ln_b  = (const float*)d_in[11];
    const float* w_f2  = (const float*)d_in[12];
    const float* b_f2  = (const float*)d_in[13];
    float* out = (float*)d_out;

    cudaFuncSetAttribute(attn_kernel,
                         cudaFuncAttributeMaxDynamicSharedMemorySize, ATTN_SMEM);

    cvt_kernel    <<<dim3(2048, 7), 256>>>(x0, x1, w_qk, w_v, w_out, w_f1, w_f2);
    bcomb_kernel  <<<4, 128>>>(b_out, w_f1, b_f1);
    wcomb_kernel  <<<dim3(4, 2), 256>>>();
    qkv_kernel    <<<dim3(4, 64, 2), 256>>>(b_qk, b_v);
    attn_kernel   <<<dim3(16, 16, 2), 256, ATTN_SMEM>>>();
    ffn1_kernel   <<<dim3(4, 64, 2), 256>>>();
    ln_gelu_kernel<<<16384, 128>>>(ln_g, ln_b);
    ffn2_kernel   <<<dim3(2, 64, 2), 256>>>(x0, x1, b_f2, out);
}

// round 15
// speedup vs baseline: 1.1991x; 1.1991x over previous
#include <cuda_runtime.h>
#include <cuda_fp16.h>
#include <mma.h>
#include <math.h>

using namespace nvcuda;

// Problem constants
#define BB    4
#define NN    2048
#define DD    256
#define HH    4
#define DHH   64
#define BH    16
#define MTOT  8192
#define QKSCALE 0.35355339059327379f  // 64^{-0.25}

// -------- scratch ----------
__device__ __half g_xh [2][MTOT * DD];
__device__ __half g_wqk[DD * DD];
__device__ __half g_wv [DD * DD];
__device__ __half g_wout[DD * DD];
__device__ __half g_wf1[4 * DD * DD];         // 512x512
__device__ __half g_wf2[2 * DD * DD];         // 512x256
__device__ __half g_wcomb[DD * 2 * DD];       // w_out @ w_f1[256:,:]  (256x512)
__device__ float  g_bcomb[2 * DD];            // b_f1 + b_out @ w_f1[256:,:]
__device__ __half g_qk [2][BH * NN * DHH];
__device__ __half g_v  [2][BH * NN * DHH];
__device__ __half g_att[2][MTOT * DD];
__device__ float  g_h  [2][MTOT * 2 * DD];
__device__ __half g_hh [2][MTOT * 2 * DD];

using FragAh  = wmma::fragment<wmma::matrix_a, 16, 16, 16, __half, wmma::row_major>;
using FragBh  = wmma::fragment<wmma::matrix_b, 16, 16, 16, __half, wmma::row_major>;
using FragBcH = wmma::fragment<wmma::matrix_b, 16, 16, 16, __half, wmma::col_major>;
using FragC16 = wmma::fragment<wmma::accumulator, 16, 16, 16, float>;

// ---- cp.async ----
__device__ __forceinline__ void cp16(void* smem_dst, const void* gsrc) {
    unsigned int s = (unsigned int)__cvta_generic_to_shared(smem_dst);
    asm volatile("cp.async.cg.shared.global [%0], [%1], 16;" :: "r"(s), "l"(gsrc));
}
#define CP_COMMIT() asm volatile("cp.async.commit_group;")
#define CP_WAIT0()  asm volatile("cp.async.wait_group 0;")

// ==========================================================================
// Kernel 0: f32 -> f16 conversion (inputs + weights)
// ==========================================================================
__global__ __launch_bounds__(256) void cvt_kernel(
    const float* __restrict__ x0, const float* __restrict__ x1,
    const float* __restrict__ wqk, const float* __restrict__ wv,
    const float* __restrict__ wout, const float* __restrict__ wf1,
    const float* __restrict__ wf2)
{
    const float* src; __half* dst; int n;
    switch (blockIdx.y) {
    case 0: src = x0;  dst = g_xh[0]; n = MTOT * DD;  break;
    case 1: src = x1;  dst = g_xh[1]; n = MTOT * DD;  break;
    case 2: src = wqk; dst = g_wqk;   n = DD * DD;    break;
    case 3: src = wv;  dst = g_wv;    n = DD * DD;    break;
    case 4: src = wout;dst = g_wout;  n = DD * DD;    break;
    case 5: src = wf1; dst = g_wf1;   n = 4 * DD * DD;break;
    default:src = wf2; dst = g_wf2;   n = 2 * DD * DD;break;
    }
    int idx = (blockIdx.x * 256 + threadIdx.x) * 4;
    if (idx < n) {
        float4 v = *(const float4*)(src + idx);
        *(__half2*)(dst + idx)     = __floats2half2_rn(v.x, v.y);
        *(__half2*)(dst + idx + 2) = __floats2half2_rn(v.z, v.w);
    }
}

// ==========================================================================
// Kernel 0b: b_comb = b_f1 + b_out @ w_f1[256:,:]   grid 4 x 128
// ==========================================================================
__global__ __launch_bounds__(128) void bcomb_kernel(
    const float* __restrict__ b_out, const float* __restrict__ w_f1,
    const float* __restrict__ b_f1)
{
    int c = blockIdx.x * 128 + threadIdx.x;
    float s = b_f1[c];
#pragma unroll 8
    for (int k = 0; k < 256; k++)
        s += b_out[k] * w_f1[(size_t)(256 + k) * 512 + c];
    g_bcomb[c] = s;
}

// ==========================================================================
// FP16 GEMM block: BM=128, BN=128, BK=32, 8 warps (2x4), warp tile 64x32.
// __launch_bounds__(256, 2): cap regs at 128 -> 2 CTAs/SM.
// ==========================================================================
#define ASH_LD 40
#define BSH_LD 136
#define ST_LD  20

__device__ __forceinline__ void gemm_core_h(const __half* As, const __half* Bs,
                                            FragC16 acc[4][2], int wr, int wc)
{
#pragma unroll
    for (int kk = 0; kk < 2; kk++) {
        FragAh af[4];
        FragBh bf[2];
#pragma unroll
        for (int i = 0; i < 4; i++)
            wmma::load_matrix_sync(af[i], As + (wr * 64 + i * 16) * ASH_LD + kk * 16, ASH_LD);
#pragma unroll
        for (int j = 0; j < 2; j++)
            wmma::load_matrix_sync(bf[j], Bs + (kk * 16) * BSH_LD + wc * 32 + j * 16, BSH_LD);
#pragma unroll
        for (int i = 0; i < 4; i++)
#pragma unroll
            for (int j = 0; j < 2; j++)
                wmma::mma_sync(acc[i][j], af[i], bf[j], acc[i][j]);
    }
}

__device__ __forceinline__ void issue_Ah(__half* As, const __half* A, int mBase,
                                         int kt, int lda, int tid)
{
#pragma unroll
    for (int it = 0; it < 2; it++) {
        int i = tid + it * 256;
        int row = i >> 2, c8 = i & 3;
        cp16(As + row * ASH_LD + c8 * 8,
             A + (size_t)(mBase + row) * lda + kt + c8 * 8);
    }
}
__device__ __forceinline__ void issue_Bh(__half* Bs, const __half* B, int kt,
                                         int cOff, int ldb, int tid)
{
#pragma unroll
    for (int it = 0; it < 2; it++) {
        int i = tid + it * 256;
        int k = i >> 4, c8 = i & 15;
        cp16(Bs + k * BSH_LD + c8 * 8,
             B + (size_t)(kt + k) * ldb + cOff + c8 * 8);
    }
}

// ==========================================================================
// Kernel 0c: w_comb = w_out @ w_f1[256:,:]  (256x512, fp16). grid (4, 2)
// ==========================================================================
__global__ __launch_bounds__(256, 2) void wcomb_kernel()
{
    __shared__ __align__(16) __half As[2][128 * ASH_LD];
    __shared__ __align__(16) __half Bs[2][32 * BSH_LD];

    const __half* A = g_wout;
    const __half* B = g_wf1 + 256 * 512;
    const int mBase = blockIdx.y * 128;
    const int cBase = blockIdx.x * 128;
    const int tid = threadIdx.x;
    const int warp = tid >> 5, lane = tid & 31;
    const int wr = warp >> 2, wc = warp & 3;

    FragC16 acc[4][2];
#pragma unroll
    for (int i = 0; i < 4; i++)
#pragma unroll
        for (int j = 0; j < 2; j++) wmma::fill_fragment(acc[i][j], 0.f);

    issue_Ah(As[0], A, mBase, 0, DD, tid);
    issue_Bh(Bs[0], B, 0, cBase, 512, tid);
    CP_COMMIT();
    int buf = 0;
    for (int kt = 0; kt < 256; kt += 32) {
        CP_WAIT0();
        __syncthreads();
        if (kt + 32 < 256) {
            issue_Ah(As[buf ^ 1], A, mBase, kt + 32, DD, tid);
            issue_Bh(Bs[buf ^ 1], B, kt + 32, cBase, 512, tid);
            CP_COMMIT();
        }
        gemm_core_h(As[buf], Bs[buf], acc, wr, wc);
        buf ^= 1;
    }
    __syncthreads();

    float* stg = (float*)As + warp * (16 * ST_LD);
    const int r = lane >> 1, c0 = (lane & 1) * 8;
#pragma unroll
    for (int i = 0; i < 4; i++)
#pragma unroll
        for (int j = 0; j < 2; j++) {
            wmma::store_matrix_sync(stg, acc[i][j], ST_LD, wmma::mem_row_major);
            __syncwarp();
            int gm = mBase + wr * 64 + i * 16 + r;
            int gc = cBase + wc * 32 + j * 16 + c0;
            const float* sp = stg + r * ST_LD + c0;
            __half* dst = g_wcomb + (size_t)gm * 512 + gc;
#pragma unroll
            for (int u = 0; u < 8; u += 2)
                *(__half2*)(dst + u) = __floats2half2_rn(sp[u], sp[u + 1]);
            __syncwarp();
        }
}

// ==========================================================================
// Kernel 1: fused QK/V projection. grid (4, 64, 2)
// Vectorized epilogue: branch hoisted per 8-col run (run never crosses a head)
// ==========================================================================
__global__ __launch_bounds__(256, 2) void qkv_kernel(
    const float* __restrict__ b_qk, const float* __restrict__ b_v)
{
    __shared__ __align__(16) __half As[2][128 * ASH_LD];
    __shared__ __align__(16) __half Bs[2][32 * BSH_LD];

    const int s = blockIdx.z;
    const __half* A = g_xh[s];
    const int mBase = blockIdx.y * 128;
    const int cBase = blockIdx.x * 128;
    const int tid = threadIdx.x;
    const int warp = tid >> 5, lane = tid & 31;
    const int wr = warp >> 2, wc = warp & 3;

    const __half* W; int cOff;
    if (cBase < 256) { W = g_wqk; cOff = cBase; }
    else             { W = g_wv;  cOff = cBase - 256; }

    FragC16 acc[4][2];
#pragma unroll
    for (int i = 0; i < 4; i++)
#pragma unroll
        for (int j = 0; j < 2; j++) wmma::fill_fragment(acc[i][j], 0.f);

    issue_Ah(As[0], A, mBase, 0, DD, tid);
    issue_Bh(Bs[0], W, 0, cOff, DD, tid);
    CP_COMMIT();
    int buf = 0;
    for (int kt = 0; kt < 256; kt += 32) {
        CP_WAIT0();
        __syncthreads();
        if (kt + 32 < 256) {
            issue_Ah(As[buf ^ 1], A, mBase, kt + 32, DD, tid);
            issue_Bh(Bs[buf ^ 1], W, kt + 32, cOff, DD, tid);
            CP_COMMIT();
        }
        gemm_core_h(As[buf], Bs[buf], acc, wr, wc);
        buf ^= 1;
    }
    __syncthreads();

    float* stg = (float*)As + warp * (16 * ST_LD);
    const int r = lane >> 1, c0 = (lane & 1) * 8;
#pragma unroll
    for (int i = 0; i < 4; i++)
#pragma unroll
        for (int j = 0; j < 2; j++) {
            wmma::store_matrix_sync(stg, acc[i][j], ST_LD, wmma::mem_row_major);
            __syncwarp();
            int gm = mBase + wr * 64 + i * 16 + r;
            int gc = cBase + wc * 32 + j * 16 + c0;   // multiple of 8
            int b = gm >> 11, n = gm & 2047;
            const float* sp = stg + r * ST_LD + c0;
            if (gc < 256) {
                int h = gc >> 6, d = gc & 63;
                __half* dst = g_qk[s] + (((size_t)(b * HH + h) * NN + n) * DHH) + d;
                float4 bb0 = *(const float4*)(b_qk + gc);
                float4 bb1 = *(const float4*)(b_qk + gc + 4);
                *(__half2*)(dst)     = __floats2half2_rn((sp[0] + bb0.x) * QKSCALE,
                                                         (sp[1] + bb0.y) * QKSCALE);
                *(__half2*)(dst + 2) = __floats2half2_rn((sp[2] + bb0.z) * QKSCALE,
                                                         (sp[3] + bb0.w) * QKSCALE);
                *(__half2*)(dst + 4) = __floats2half2_rn((sp[4] + bb1.x) * QKSCALE,
                                                         (sp[5] + bb1.y) * QKSCALE);
                *(__half2*)(dst + 6) = __floats2half2_rn((sp[6] + bb1.z) * QKSCALE,
                                                         (sp[7] + bb1.w) * QKSCALE);
            } else {
                int c2 = gc - 256;
                int h = c2 >> 6, d = c2 & 63;
                __half* dst = g_v[s] + (((size_t)(b * HH + h) * NN + n) * DHH) + d;
                float4 bb0 = *(const float4*)(b_v + c2);
                float4 bb1 = *(const float4*)(b_v + c2 + 4);
                *(__half2*)(dst)     = __floats2half2_rn(sp[0] + bb0.x, sp[1] + bb0.y);
                *(__half2*)(dst + 2) = __floats2half2_rn(sp[2] + bb0.z, sp[3] + bb0.w);
                *(__half2*)(dst + 4) = __floats2half2_rn(sp[4] + bb1.x, sp[5] + bb1.y);
                *(__half2*)(dst + 6) = __floats2half2_rn(sp[6] + bb1.z, sp[7] + bb1.w);
            }
            __syncwarp();
        }
}

// ==========================================================================
// Kernel 2: attention (fp16 wmma, f32 S/exp, no-max softmax) — R12 version.
// grid (16, 16, 2) block 256.  cp.async double-buffered K/V, per-warp rows.
// smem: Ks2 2x[64x72h] | Vs2 2x[64x72h] | Ps[128x72 f32] | Ph[128x72h]
// ==========================================================================
#define KV_LD 72
#define PS_LD 72
#define PH_LD 72
#define ATTN_SMEM (18432 + 18432 + 36864 + 18432)   // 92160

__global__ __launch_bounds__(256) void attn_kernel()
{
    extern __shared__ char smc[];
    __half* Ks2 = (__half*)smc;
    __half* Vs2 = (__half*)(smc + 18432);
    float*  Ps  = (float*) (smc + 36864);
    __half* Ph  = (__half*)(smc + 73728);

    const int s  = blockIdx.z;
    const int bh = blockIdx.y;
    const int qb = blockIdx.x;
    const __half* Q = g_qk[s]     + (size_t)bh * NN * DHH + (size_t)qb * 128 * DHH;
    const __half* K = g_qk[s ^ 1] + (size_t)bh * NN * DHH;
    const __half* V = g_v [s ^ 1] + (size_t)bh * NN * DHH;

    const int tid = threadIdx.x;
    const int w = tid >> 5;
    const int lane = tid & 31;
    const int myrow = w * 16 + (lane >> 1);
    const int ecb   = (lane & 1) * 32;

    // stage Q into Ph
#pragma unroll
    for (int it = 0; it < 4; it++) {
        int i = tid + it * 256;
        int r = i >> 3, c8 = i & 7;
        cp16(Ph + r * PH_LD + c8 * 8, Q + r * 64 + c8 * 8);
    }
    // KV block 0
#pragma unroll
    for (int it = 0; it < 2; it++) {
        int i = tid + it * 256;
        int r = i >> 3, c8 = i & 7;
        cp16(Ks2 + r * KV_LD + c8 * 8, K + r * 64 + c8 * 8);
        cp16(Vs2 + r * KV_LD + c8 * 8, V + r * 64 + c8 * 8);
    }
    CP_COMMIT();
    CP_WAIT0();
    __syncthreads();

    FragAh qf[4];
#pragma unroll
    for (int kk = 0; kk < 4; kk++)
        wmma::load_matrix_sync(qf[kk], Ph + (w * 16) * PH_LD + kk * 16, PH_LD);

    FragC16 o[4];
#pragma unroll
    for (int c = 0; c < 4; c++) wmma::fill_fragment(o[c], 0.f);
    float lsum = 0.f;
    int buf = 0;

    for (int kb = 0; kb < NN / 64; kb++) {
        CP_WAIT0();
        __syncthreads();
        if (kb + 1 < NN / 64) {
            const __half* Kb = K + (size_t)(kb + 1) * 64 * 64;
            const __half* Vb = V + (size_t)(kb + 1) * 64 * 64;
            __half* Kd = Ks2 + (buf ^ 1) * 64 * KV_LD;
            __half* Vd = Vs2 + (buf ^ 1) * 64 * KV_LD;
#pragma unroll
            for (int it = 0; it < 2; it++) {
                int i = tid + it * 256;
                int r = i >> 3, c8 = i & 7;
                cp16(Kd + r * KV_LD + c8 * 8, Kb + r * 64 + c8 * 8);
                cp16(Vd + r * KV_LD + c8 * 8, Vb + r * 64 + c8 * 8);
            }
            CP_COMMIT();
        }
        const __half* Ksb = Ks2 + buf * 64 * KV_LD;
        const __half* Vsb = Vs2 + buf * 64 * KV_LD;

        // S = Q @ K^T (per warp 16x64), f32 accum
        FragC16 sa[4];
#pragma unroll
        for (int c = 0; c < 4; c++) wmma::fill_fragment(sa[c], 0.f);
#pragma unroll
        for (int kk = 0; kk < 4; kk++) {
#pragma unroll
            for (int c = 0; c < 4; c++) {
                FragBcH bf;
                wmma::load_matrix_sync(bf, Ksb + (c * 16) * KV_LD + kk * 16, KV_LD);
                wmma::mma_sync(sa[c], qf[kk], bf, sa[c]);
            }
        }
#pragma unroll
        for (int c = 0; c < 4; c++)
            wmma::store_matrix_sync(Ps + (w * 16) * PS_LD + c * 16, sa[c], PS_LD,
                                    wmma::mem_row_major);
        __syncwarp();

        // exp on OWN rows (f32), write P as half, row-sum via shfl
        {
            float rs = 0.f;
            const float* sP = Ps + myrow * PS_LD + ecb;
            __half2* dP = (__half2*)(Ph + myrow * PH_LD + ecb);
#pragma unroll
            for (int c = 0; c < 32; c += 2) {
                float p0 = __expf(sP[c]);
                float p1 = __expf(sP[c + 1]);
                rs += p0 + p1;
                dP[c >> 1] = __floats2half2_rn(p0, p1);
            }
            rs += __shfl_xor_sync(0xffffffffu, rs, 1);
            lsum += rs;
        }
        __syncwarp();

        // O += P @ V
#pragma unroll
        for (int kk = 0; kk < 4; kk++) {
            FragAh af;
            wmma::load_matrix_sync(af, Ph + (w * 16) * PH_LD + kk * 16, PH_LD);
#pragma unroll
            for (int c = 0; c < 4; c++) {
                FragBh bf;
                wmma::load_matrix_sync(bf, Vsb + (kk * 16) * KV_LD + c * 16, KV_LD);
                wmma::mma_sync(o[c], af, bf, o[c]);
            }
        }
        buf ^= 1;
    }

    // finalize
#pragma unroll
    for (int c = 0; c < 4; c++)
        wmma::store_matrix_sync(Ps + (w * 16) * PS_LD + c * 16, o[c], PS_LD,
                                wmma::mem_row_major);
    __syncwarp();

    const int b = bh >> 2, h = bh & 3;
    {
        float inv = 1.f / lsum;
        int n = qb * 128 + myrow;
        __half* dst = g_att[s] + ((size_t)(b * NN + n)) * DD + h * 64 + ecb;
        const float* src = Ps + myrow * PS_LD + ecb;
#pragma unroll
        for (int c = 0; c < 32; c += 2)
            *(__half2*)(dst + c) = __floats2half2_rn(src[c] * inv, src[c + 1] * inv);
    }
}

// ==========================================================================
// Kernel 4: FFN1.  h = x @ w_f1_top + att @ w_comb + b_comb  (K=512)
// grid (4, 64, 2)
// ==========================================================================
__global__ __launch_bounds__(256, 2) void ffn1_kernel()
{
    __shared__ __align__(16) __half As[2][128 * ASH_LD];
    __shared__ __align__(16) __half Bs[2][32 * BSH_LD];

    const int s = blockIdx.z;
    const __half* X  = g_xh[s];
    const __half* At = g_att[s];
    const int mBase = blockIdx.y * 128;
    const int cBase = blockIdx.x * 128;
    const int tid = threadIdx.x;
    const int warp = tid >> 5, lane = tid & 31;
    const int wr = warp >> 2, wc = warp & 3;

    FragC16 acc[4][2];
#pragma unroll
    for (int i = 0; i < 4; i++)
#pragma unroll
        for (int j = 0; j < 2; j++) wmma::fill_fragment(acc[i][j], 0.f);

    issue_Ah(As[0], X, mBase, 0, DD, tid);
    issue_Bh(Bs[0], g_wf1, 0, cBase, 512, tid);
    CP_COMMIT();
    int buf = 0;
    for (int kt = 0; kt < 512; kt += 32) {
        CP_WAIT0();
        __syncthreads();
        if (kt + 32 < 512) {
            int kn = kt + 32;
            const __half* Asrc = (kn < 256) ? X : At;
            int kOff = (kn < 256) ? kn : kn - 256;
            const __half* Bsrc = (kn < 256) ? g_wf1 : g_wcomb;
            int kB = (kn < 256) ? kn : kn - 256;
            issue_Ah(As[buf ^ 1], Asrc, mBase, kOff, DD, tid);
            issue_Bh(Bs[buf ^ 1], Bsrc, kB, cBase, 512, tid);
            CP_COMMIT();
        }
        gemm_core_h(As[buf], Bs[buf], acc, wr, wc);
        buf ^= 1;
    }
    __syncthreads();

    float* stg = (float*)As + warp * (16 * ST_LD);
    const int r = lane >> 1, c0 = (lane & 1) * 8;
#pragma unroll
    for (int i = 0; i < 4; i++)
#pragma unroll
        for (int j = 0; j < 2; j++) {
            wmma::store_matrix_sync(stg, acc[i][j], ST_LD, wmma::mem_row_major);
            __syncwarp();
            int gm = mBase + wr * 64 + i * 16 + r;
            int gc = cBase + wc * 32 + j * 16 + c0;
            float4 b0 = *(const float4*)(g_bcomb + gc);
            float4 b1 = *(const float4*)(g_bcomb + gc + 4);
            const float* sp = stg + r * ST_LD + c0;
            float4 v0 = make_float4(sp[0] + b0.x, sp[1] + b0.y, sp[2] + b0.z, sp[3] + b0.w);
            float4 v1 = make_float4(sp[4] + b1.x, sp[5] + b1.y, sp[6] + b1.z, sp[7] + b1.w);
            *(float4*)(&g_h[s][(size_t)gm * (2 * DD) + gc])     = v0;
            *(float4*)(&g_h[s][(size_t)gm * (2 * DD) + gc + 4]) = v1;
            __syncwarp();
        }
}

// ==========================================================================
// Kernel 5: LayerNorm(512) + exact GELU; f32 g_h -> half g_hh. grid 16384
// ==========================================================================
__global__ __launch_bounds__(128) void ln_gelu_kernel(
    const float* __restrict__ g, const float* __restrict__ bta)
{
    const int row = blockIdx.x;
    const int s = row >> 13;
    const int rr = row & 8191;
    const float* h = g_h[s] + (size_t)rr * 512;
    const int tid = threadIdx.x;

    float4 t = reinterpret_cast<const float4*>(h)[tid];
    float sum = t.x + t.y + t.z + t.w;
    float sq  = t.x * t.x + t.y * t.y + t.z * t.z + t.w * t.w;
#pragma unroll
    for (int off = 16; off > 0; off >>= 1) {
        sum += __shfl_xor_sync(0xffffffffu, sum, off);
        sq  += __shfl_xor_sync(0xffffffffu, sq,  off);
    }
    __shared__ float ssum[4], ssq[4];
    const int w = tid >> 5;
    if ((tid & 31) == 0) { ssum[w] = sum; ssq[w] = sq; }
    __syncthreads();
    sum = ssum[0] + ssum[1] + ssum[2] + ssum[3];
    sq  = ssq[0]  + ssq[1]  + ssq[2]  + ssq[3];

    const float mu   = sum * (1.f / 512.f);
    const float var  = sq * (1.f / 512.f) - mu * mu;
    const float rstd = rsqrtf(var + 1e-5f);

    float4 gg = reinterpret_cast<const float4*>(g)[tid];
    float4 bb = reinterpret_cast<const float4*>(bta)[tid];
    auto act = [&](float v, float gv, float bv) {
        float y = (v - mu) * rstd * gv + bv;
        return 0.5f * y * (1.f + erff(y * 0.70710678118654752f));
    };
    float r0 = act(t.x, gg.x, bb.x);
    float r1 = act(t.y, gg.y, bb.y);
    float r2 = act(t.z, gg.z, bb.z);
    float r3 = act(t.w, gg.w, bb.w);

    __half2* dst = (__half2*)(g_hh[s] + (size_t)rr * 512 + tid * 4);
    dst[0] = __floats2half2_rn(r0, r1);
    dst[1] = __floats2half2_rn(r2, r3);
}

// ==========================================================================
// Kernel 6: FFN2 + residual.  out = x + hh @ w_f2 + b_f2 (K=512). grid (2,64,2)
// ==========================================================================
__global__ __launch_bounds__(256, 2) void ffn2_kernel(
    const float* __restrict__ x0, const float* __restrict__ x1,
    const float* __restrict__ bias, float* __restrict__ out)
{
    __shared__ __align__(16) __half As[2][128 * ASH_LD];
    __shared__ __align__(16) __half Bs[2][32 * BSH_LD];

    const int s = blockIdx.z;
    const float* X = s ? x1 : x0;
    const __half* A = g_hh[s];
    const int mBase = blockIdx.y * 128;
    const int cBase = blockIdx.x * 128;
    const int tid = threadIdx.x;
    const int warp = tid >> 5, lane = tid & 31;
    const int wr = warp >> 2, wc = warp & 3;

    FragC16 acc[4][2];
#pragma unroll
    for (int i = 0; i < 4; i++)
#pragma unroll
        for (int j = 0; j < 2; j++) wmma::fill_fragment(acc[i][j], 0.f);

    issue_Ah(As[0], A, mBase, 0, 2 * DD, tid);
    issue_Bh(Bs[0], g_wf2, 0, cBase, DD, tid);
    CP_COMMIT();
    int buf = 0;
    for (int kt = 0; kt < 512; kt += 32) {
        CP_WAIT0();
        __syncthreads();
        if (kt + 32 < 512) {
            issue_Ah(As[buf ^ 1], A, mBase, kt + 32, 2 * DD, tid);
            issue_Bh(Bs[buf ^ 1], g_wf2, kt + 32, cBase, DD, tid);
            CP_COMMIT();
        }
        gemm_core_h(As[buf], Bs[buf], acc, wr, wc);
        buf ^= 1;
    }
    __syncthreads();

    float* stg = (float*)As + warp * (16 * ST_LD);
    const int r = lane >> 1, c0 = (lane & 1) * 8;
#pragma unroll
    for (int i = 0; i < 4; i++)
#pragma unroll
        for (int j = 0; j < 2; j++) {
            wmma::store_matrix_sync(stg, acc[i][j], ST_LD, wmma::mem_row_major);
            __syncwarp();
            int gm = mBase + wr * 64 + i * 16 + r;
            int gc = cBase + wc * 32 + j * 16 + c0;
            float4 b0 = *(const float4*)(bias + gc);
            float4 b1 = *(const float4*)(bias + gc + 4);
            float4 x0v = *(const float4*)(X + (size_t)gm * DD + gc);
            float4 x1v = *(const float4*)(X + (size_t)gm * DD + gc + 4);
            const float* sp = stg + r * ST_LD + c0;
            float4 v0 = make_float4(sp[0] + b0.x + x0v.x, sp[1] + b0.y + x0v.y,
                                    sp[2] + b0.z + x0v.z, sp[3] + b0.w + x0v.w);
            float4 v1 = make_float4(sp[4] + b1.x + x1v.x, sp[5] + b1.y + x1v.y,
                                    sp[6] + b1.z + x1v.z, sp[7] + b1.w + x1v.w);
            *(float4*)(out + (size_t)s * MTOT * DD + (size_t)gm * DD + gc)     = v0;
            *(float4*)(out + (size_t)s * MTOT * DD + (size_t)gm * DD + gc + 4) = v1;
            __syncwarp();
        }
}

// ==========================================================================
extern "C" void kernel_launch(void* const* d_in, const int* in_sizes, int n_in,
                              void* d_out, int out_size)
{
    const float* x0    = (const float*)d_in[0];
    const float* x1    = (const float*)d_in[1];
    const float* w_qk  = (const float*)d_in[2];
    const float* b_qk  = (const float*)d_in[3];
    const float* w_v   = (const float*)d_in[4];
    const float* b_v   = (const float*)d_in[5];
    const float* w_out = (const float*)d_in[6];
    const float* b_out = (const float*)d_in[7];
    const float* w_f1  = (const float*)d_in[8];
    const float* b_f1  = (const float*)d_in[9];
    const float* ln_g  = (const float*)d_in[10];
    const float* ln_b  = (const float*)d_in[11];
    const float* w_f2  = (const float*)d_in[12];
    const float* b_f2  = (const float*)d_in[13];
    float* out = (float*)d_out;

    cudaFuncSetAttribute(attn_kernel,
                         cudaFuncAttributeMaxDynamicSharedMemorySize, ATTN_SMEM);

    cvt_kernel    <<<dim3(2048, 7), 256>>>(x0, x1, w_qk, w_v, w_out, w_f1, w_f2);
    bcomb_kernel  <<<4, 128>>>(b_out, w_f1, b_f1);
    wcomb_kernel  <<<dim3(4, 2), 256>>>();
    qkv_kernel    <<<dim3(4, 64, 2), 256>>>(b_qk, b_v);
    attn_kernel   <<<dim3(16, 16, 2), 256, ATTN_SMEM>>>();
    ffn1_kernel   <<<dim3(4, 64, 2), 256>>>();
    ln_gelu_kernel<<<16384, 128>>>(ln_g, ln_b);
    ffn2_kernel   <<<dim3(2, 64, 2), 256>>>(x0, x1, b_f2, out);
}

// round 17
// speedup vs baseline: 1.2473x; 1.0402x over previous
#include <cuda_runtime.h>
#include <cuda_fp16.h>
#include <mma.h>
#include <math.h>

using namespace nvcuda;

// Problem constants
#define BB    4
#define NN    2048
#define DD    256
#define HH    4
#define DHH   64
#define BH    16
#define MTOT  8192
#define QKSCALE 0.35355339059327379f  // 64^{-0.25}

// -------- scratch ----------
__device__ __half g_xh [2][MTOT * DD];
__device__ __half g_wqk[DD * DD];
__device__ __half g_wv [DD * DD];
__device__ __half g_wout[DD * DD];
__device__ __half g_wf1[4 * DD * DD];         // 512x512
__device__ __half g_wf2[2 * DD * DD];         // 512x256
__device__ __half g_wcomb[DD * 2 * DD];       // w_out @ w_f1[256:,:]  (256x512)
__device__ float  g_bcomb[2 * DD];            // b_f1 + b_out @ w_f1[256:,:]
__device__ __half g_qk [2][BH * NN * DHH];
__device__ __half g_v  [2][BH * NN * DHH];
__device__ __half g_att[2][MTOT * DD];
__device__ float  g_h  [2][MTOT * 2 * DD];
__device__ __half g_hh [2][MTOT * 2 * DD];

using FragAh  = wmma::fragment<wmma::matrix_a, 16, 16, 16, __half, wmma::row_major>;
using FragBh  = wmma::fragment<wmma::matrix_b, 16, 16, 16, __half, wmma::row_major>;
using FragBcH = wmma::fragment<wmma::matrix_b, 16, 16, 16, __half, wmma::col_major>;
using FragC16 = wmma::fragment<wmma::accumulator, 16, 16, 16, float>;

// ---- cp.async ----
__device__ __forceinline__ void cp16(void* smem_dst, const void* gsrc) {
    unsigned int s = (unsigned int)__cvta_generic_to_shared(smem_dst);
    asm volatile("cp.async.cg.shared.global [%0], [%1], 16;" :: "r"(s), "l"(gsrc));
}
#define CP_COMMIT() asm volatile("cp.async.commit_group;")
#define CP_WAIT0()  asm volatile("cp.async.wait_group 0;")

// ==========================================================================
// Kernel 0: f32 -> f16 conversion (inputs + weights)
// ==========================================================================
__global__ __launch_bounds__(256) void cvt_kernel(
    const float* __restrict__ x0, const float* __restrict__ x1,
    const float* __restrict__ wqk, const float* __restrict__ wv,
    const float* __restrict__ wout, const float* __restrict__ wf1,
    const float* __restrict__ wf2)
{
    const float* src; __half* dst; int n;
    switch (blockIdx.y) {
    case 0: src = x0;  dst = g_xh[0]; n = MTOT * DD;  break;
    case 1: src = x1;  dst = g_xh[1]; n = MTOT * DD;  break;
    case 2: src = wqk; dst = g_wqk;   n = DD * DD;    break;
    case 3: src = wv;  dst = g_wv;    n = DD * DD;    break;
    case 4: src = wout;dst = g_wout;  n = DD * DD;    break;
    case 5: src = wf1; dst = g_wf1;   n = 4 * DD * DD;break;
    default:src = wf2; dst = g_wf2;   n = 2 * DD * DD;break;
    }
    int idx = (blockIdx.x * 256 + threadIdx.x) * 4;
    if (idx < n) {
        float4 v = *(const float4*)(src + idx);
        *(__half2*)(dst + idx)     = __floats2half2_rn(v.x, v.y);
        *(__half2*)(dst + idx + 2) = __floats2half2_rn(v.z, v.w);
    }
}

// ==========================================================================
// Kernel 0b: b_comb = b_f1 + b_out @ w_f1[256:,:]   grid 4 x 128
// ==========================================================================
__global__ __launch_bounds__(128) void bcomb_kernel(
    const float* __restrict__ b_out, const float* __restrict__ w_f1,
    const float* __restrict__ b_f1)
{
    int c = blockIdx.x * 128 + threadIdx.x;
    float s = b_f1[c];
#pragma unroll 8
    for (int k = 0; k < 256; k++)
        s += b_out[k] * w_f1[(size_t)(256 + k) * 512 + c];
    g_bcomb[c] = s;
}

// ==========================================================================
// FP16 GEMM block: BM=128, BN=128, BK=32, 8 warps (2x4), warp tile 64x32.
// __launch_bounds__(256, 2): cap regs at 128 -> 2 CTAs/SM.
// ==========================================================================
#define ASH_LD 40
#define BSH_LD 136
#define ST_LD  20

__device__ __forceinline__ void gemm_core_h(const __half* As, const __half* Bs,
                                            FragC16 acc[4][2], int wr, int wc)
{
#pragma unroll
    for (int kk = 0; kk < 2; kk++) {
        FragAh af[4];
        FragBh bf[2];
#pragma unroll
        for (int i = 0; i < 4; i++)
            wmma::load_matrix_sync(af[i], As + (wr * 64 + i * 16) * ASH_LD + kk * 16, ASH_LD);
#pragma unroll
        for (int j = 0; j < 2; j++)
            wmma::load_matrix_sync(bf[j], Bs + (kk * 16) * BSH_LD + wc * 32 + j * 16, BSH_LD);
#pragma unroll
        for (int i = 0; i < 4; i++)
#pragma unroll
            for (int j = 0; j < 2; j++)
                wmma::mma_sync(acc[i][j], af[i], bf[j], acc[i][j]);
    }
}

__device__ __forceinline__ void issue_Ah(__half* As, const __half* A, int mBase,
                                         int kt, int lda, int tid)
{
#pragma unroll
    for (int it = 0; it < 2; it++) {
        int i = tid + it * 256;
        int row = i >> 2, c8 = i & 3;
        cp16(As + row * ASH_LD + c8 * 8,
             A + (size_t)(mBase + row) * lda + kt + c8 * 8);
    }
}
__device__ __forceinline__ void issue_Bh(__half* Bs, const __half* B, int kt,
                                         int cOff, int ldb, int tid)
{
#pragma unroll
    for (int it = 0; it < 2; it++) {
        int i = tid + it * 256;
        int k = i >> 4, c8 = i & 15;
        cp16(Bs + k * BSH_LD + c8 * 8,
             B + (size_t)(kt + k) * ldb + cOff + c8 * 8);
    }
}

// ==========================================================================
// Kernel 0c: w_comb = w_out @ w_f1[256:,:]  (256x512, fp16). grid (4, 2)
// ==========================================================================
__global__ __launch_bounds__(256, 2) void wcomb_kernel()
{
    __shared__ __align__(16) __half As[2][128 * ASH_LD];
    __shared__ __align__(16) __half Bs[2][32 * BSH_LD];

    const __half* A = g_wout;
    const __half* B = g_wf1 + 256 * 512;
    const int mBase = blockIdx.y * 128;
    const int cBase = blockIdx.x * 128;
    const int tid = threadIdx.x;
    const int warp = tid >> 5, lane = tid & 31;
    const int wr = warp >> 2, wc = warp & 3;

    FragC16 acc[4][2];
#pragma unroll
    for (int i = 0; i < 4; i++)
#pragma unroll
        for (int j = 0; j < 2; j++) wmma::fill_fragment(acc[i][j], 0.f);

    issue_Ah(As[0], A, mBase, 0, DD, tid);
    issue_Bh(Bs[0], B, 0, cBase, 512, tid);
    CP_COMMIT();
    int buf = 0;
    for (int kt = 0; kt < 256; kt += 32) {
        CP_WAIT0();
        __syncthreads();
        if (kt + 32 < 256) {
            issue_Ah(As[buf ^ 1], A, mBase, kt + 32, DD, tid);
            issue_Bh(Bs[buf ^ 1], B, kt + 32, cBase, 512, tid);
            CP_COMMIT();
        }
        gemm_core_h(As[buf], Bs[buf], acc, wr, wc);
        buf ^= 1;
    }
    __syncthreads();

    float* stg = (float*)As + warp * (16 * ST_LD);
    const int r = lane >> 1, c0 = (lane & 1) * 8;
#pragma unroll
    for (int i = 0; i < 4; i++)
#pragma unroll
        for (int j = 0; j < 2; j++) {
            wmma::store_matrix_sync(stg, acc[i][j], ST_LD, wmma::mem_row_major);
            __syncwarp();
            int gm = mBase + wr * 64 + i * 16 + r;
            int gc = cBase + wc * 32 + j * 16 + c0;
            const float* sp = stg + r * ST_LD + c0;
            __half* dst = g_wcomb + (size_t)gm * 512 + gc;
#pragma unroll
            for (int u = 0; u < 8; u += 2)
                *(__half2*)(dst + u) = __floats2half2_rn(sp[u], sp[u + 1]);
            __syncwarp();
        }
}

// ==========================================================================
// Kernel 1: fused QK/V projection. grid (4, 64, 2)
// ==========================================================================
__global__ __launch_bounds__(256, 2) void qkv_kernel(
    const float* __restrict__ b_qk, const float* __restrict__ b_v)
{
    __shared__ __align__(16) __half As[2][128 * ASH_LD];
    __shared__ __align__(16) __half Bs[2][32 * BSH_LD];

    const int s = blockIdx.z;
    const __half* A = g_xh[s];
    const int mBase = blockIdx.y * 128;
    const int cBase = blockIdx.x * 128;
    const int tid = threadIdx.x;
    const int warp = tid >> 5, lane = tid & 31;
    const int wr = warp >> 2, wc = warp & 3;

    const __half* W; int cOff;
    if (cBase < 256) { W = g_wqk; cOff = cBase; }
    else             { W = g_wv;  cOff = cBase - 256; }

    FragC16 acc[4][2];
#pragma unroll
    for (int i = 0; i < 4; i++)
#pragma unroll
        for (int j = 0; j < 2; j++) wmma::fill_fragment(acc[i][j], 0.f);

    issue_Ah(As[0], A, mBase, 0, DD, tid);
    issue_Bh(Bs[0], W, 0, cOff, DD, tid);
    CP_COMMIT();
    int buf = 0;
    for (int kt = 0; kt < 256; kt += 32) {
        CP_WAIT0();
        __syncthreads();
        if (kt + 32 < 256) {
            issue_Ah(As[buf ^ 1], A, mBase, kt + 32, DD, tid);
            issue_Bh(Bs[buf ^ 1], W, kt + 32, cOff, DD, tid);
            CP_COMMIT();
        }
        gemm_core_h(As[buf], Bs[buf], acc, wr, wc);
        buf ^= 1;
    }
    __syncthreads();

    float* stg = (float*)As + warp * (16 * ST_LD);
    const int r = lane >> 1, c0 = (lane & 1) * 8;
#pragma unroll
    for (int i = 0; i < 4; i++)
#pragma unroll
        for (int j = 0; j < 2; j++) {
            wmma::store_matrix_sync(stg, acc[i][j], ST_LD, wmma::mem_row_major);
            __syncwarp();
            int gm = mBase + wr * 64 + i * 16 + r;
            int gc = cBase + wc * 32 + j * 16 + c0;   // multiple of 8
            int b = gm >> 11, n = gm & 2047;
            const float* sp = stg + r * ST_LD + c0;
            if (gc < 256) {
                int h = gc >> 6, d = gc & 63;
                __half* dst = g_qk[s] + (((size_t)(b * HH + h) * NN + n) * DHH) + d;
                float4 bb0 = *(const float4*)(b_qk + gc);
                float4 bb1 = *(const float4*)(b_qk + gc + 4);
                *(__half2*)(dst)     = __floats2half2_rn((sp[0] + bb0.x) * QKSCALE,
                                                         (sp[1] + bb0.y) * QKSCALE);
                *(__half2*)(dst + 2) = __floats2half2_rn((sp[2] + bb0.z) * QKSCALE,
                                                         (sp[3] + bb0.w) * QKSCALE);
                *(__half2*)(dst + 4) = __floats2half2_rn((sp[4] + bb1.x) * QKSCALE,
                                                         (sp[5] + bb1.y) * QKSCALE);
                *(__half2*)(dst + 6) = __floats2half2_rn((sp[6] + bb1.z) * QKSCALE,
                                                         (sp[7] + bb1.w) * QKSCALE);
            } else {
                int c2 = gc - 256;
                int h = c2 >> 6, d = c2 & 63;
                __half* dst = g_v[s] + (((size_t)(b * HH + h) * NN + n) * DHH) + d;
                float4 bb0 = *(const float4*)(b_v + c2);
                float4 bb1 = *(const float4*)(b_v + c2 + 4);
                *(__half2*)(dst)     = __floats2half2_rn(sp[0] + bb0.x, sp[1] + bb0.y);
                *(__half2*)(dst + 2) = __floats2half2_rn(sp[2] + bb0.z, sp[3] + bb0.w);
                *(__half2*)(dst + 4) = __floats2half2_rn(sp[4] + bb1.x, sp[5] + bb1.y);
                *(__half2*)(dst + 6) = __floats2half2_rn(sp[6] + bb1.z, sp[7] + bb1.w);
            }
            __syncwarp();
        }
}

// ==========================================================================
// Kernel 2: attention (fp16 wmma, f32 S/exp, no-max softmax).
// grid (16, 16, 2) block 256, __launch_bounds__(256,2) -> 2 CTAs/SM.
// PS_LD=68 (vs 72): row bank-shift 4 instead of 8 -> 4-way (was 8-way)
// conflicts in the exp phase.
// smem: Ks2 2x[64x72h] | Vs2 2x[64x72h] | Ps[128x68 f32] | Ph[128x72h]
// ==========================================================================
#define KV_LD 72
#define PS_LD 68
#define PH_LD 72
#define ATTN_SMEM (18432 + 18432 + 34816 + 18432)   // 90112 (x2 = 176KB/SM)

__global__ __launch_bounds__(256, 2) void attn_kernel()
{
    extern __shared__ char smc[];
    __half* Ks2 = (__half*)smc;
    __half* Vs2 = (__half*)(smc + 18432);
    float*  Ps  = (float*) (smc + 36864);         // 128 x 68 f32
    __half* Ph  = (__half*)(smc + 71680);         // 128 x 72 half

    const int s  = blockIdx.z;
    const int bh = blockIdx.y;
    const int qb = blockIdx.x;
    const __half* Q = g_qk[s]     + (size_t)bh * NN * DHH + (size_t)qb * 128 * DHH;
    const __half* K = g_qk[s ^ 1] + (size_t)bh * NN * DHH;
    const __half* V = g_v [s ^ 1] + (size_t)bh * NN * DHH;

    const int tid = threadIdx.x;
    const int w = tid >> 5;
    const int lane = tid & 31;
    const int myrow = w * 16 + (lane >> 1);
    const int ecb   = (lane & 1) * 32;

    // stage Q into Ph
#pragma unroll
    for (int it = 0; it < 4; it++) {
        int i = tid + it * 256;
        int r = i >> 3, c8 = i & 7;
        cp16(Ph + r * PH_LD + c8 * 8, Q + r * 64 + c8 * 8);
    }
    // KV block 0
#pragma unroll
    for (int it = 0; it < 2; it++) {
        int i = tid + it * 256;
        int r = i >> 3, c8 = i & 7;
        cp16(Ks2 + r * KV_LD + c8 * 8, K + r * 64 + c8 * 8);
        cp16(Vs2 + r * KV_LD + c8 * 8, V + r * 64 + c8 * 8);
    }
    CP_COMMIT();
    CP_WAIT0();
    __syncthreads();

    FragAh qf[4];
#pragma unroll
    for (int kk = 0; kk < 4; kk++)
        wmma::load_matrix_sync(qf[kk], Ph + (w * 16) * PH_LD + kk * 16, PH_LD);

    FragC16 o[4];
#pragma unroll
    for (int c = 0; c < 4; c++) wmma::fill_fragment(o[c], 0.f);
    float lsum = 0.f;
    int buf = 0;

    for (int kb = 0; kb < NN / 64; kb++) {
        CP_WAIT0();
        __syncthreads();
        if (kb + 1 < NN / 64) {
            const __half* Kb = K + (size_t)(kb + 1) * 64 * 64;
            const __half* Vb = V + (size_t)(kb + 1) * 64 * 64;
            __half* Kd = Ks2 + (buf ^ 1) * 64 * KV_LD;
            __half* Vd = Vs2 + (buf ^ 1) * 64 * KV_LD;
#pragma unroll
            for (int it = 0; it < 2; it++) {
                int i = tid + it * 256;
                int r = i >> 3, c8 = i & 7;
                cp16(Kd + r * KV_LD + c8 * 8, Kb + r * 64 + c8 * 8);
                cp16(Vd + r * KV_LD + c8 * 8, Vb + r * 64 + c8 * 8);
            }
            CP_COMMIT();
        }
        const __half* Ksb = Ks2 + buf * 64 * KV_LD;
        const __half* Vsb = Vs2 + buf * 64 * KV_LD;

        // S = Q @ K^T (per warp 16x64), f32 accum
        FragC16 sa[4];
#pragma unroll
        for (int c = 0; c < 4; c++) wmma::fill_fragment(sa[c], 0.f);
#pragma unroll
        for (int kk = 0; kk < 4; kk++) {
#pragma unroll
            for (int c = 0; c < 4; c++) {
                FragBcH bf;
                wmma::load_matrix_sync(bf, Ksb + (c * 16) * KV_LD + kk * 16, KV_LD);
                wmma::mma_sync(sa[c], qf[kk], bf, sa[c]);
            }
        }
#pragma unroll
        for (int c = 0; c < 4; c++)
            wmma::store_matrix_sync(Ps + (w * 16) * PS_LD + c * 16, sa[c], PS_LD,
                                    wmma::mem_row_major);
        __syncwarp();

        // exp on OWN rows (f32), write P as half, row-sum via shfl
        {
            float rs = 0.f;
            const float* sP = Ps + myrow * PS_LD + ecb;
            __half2* dP = (__half2*)(Ph + myrow * PH_LD + ecb);
#pragma unroll
            for (int c = 0; c < 32; c += 2) {
                float p0 = __expf(sP[c]);
                float p1 = __expf(sP[c + 1]);
                rs += p0 + p1;
                dP[c >> 1] = __floats2half2_rn(p0, p1);
            }
            rs += __shfl_xor_sync(0xffffffffu, rs, 1);
            lsum += rs;
        }
        __syncwarp();

        // O += P @ V
#pragma unroll
        for (int kk = 0; kk < 4; kk++) {
            FragAh af;
            wmma::load_matrix_sync(af, Ph + (w * 16) * PH_LD + kk * 16, PH_LD);
#pragma unroll
            for (int c = 0; c < 4; c++) {
                FragBh bf;
                wmma::load_matrix_sync(bf, Vsb + (kk * 16) * KV_LD + c * 16, KV_LD);
                wmma::mma_sync(o[c], af, bf, o[c]);
            }
        }
        buf ^= 1;
    }

    // finalize
#pragma unroll
    for (int c = 0; c < 4; c++)
        wmma::store_matrix_sync(Ps + (w * 16) * PS_LD + c * 16, o[c], PS_LD,
                                wmma::mem_row_major);
    __syncwarp();

    const int b = bh >> 2, h = bh & 3;
    {
        float inv = 1.f / lsum;
        int n = qb * 128 + myrow;
        __half* dst = g_att[s] + ((size_t)(b * NN + n)) * DD + h * 64 + ecb;
        const float* src = Ps + myrow * PS_LD + ecb;
#pragma unroll
        for (int c = 0; c < 32; c += 2)
            *(__half2*)(dst + c) = __floats2half2_rn(src[c] * inv, src[c + 1] * inv);
    }
}

// ==========================================================================
// Kernel 4: FFN1.  h = x @ w_f1_top + att @ w_comb + b_comb  (K=512)
// grid (4, 64, 2)
// ==========================================================================
__global__ __launch_bounds__(256, 2) void ffn1_kernel()
{
    __shared__ __align__(16) __half As[2][128 * ASH_LD];
    __shared__ __align__(16) __half Bs[2][32 * BSH_LD];

    const int s = blockIdx.z;
    const __half* X  = g_xh[s];
    const __half* At = g_att[s];
    const int mBase = blockIdx.y * 128;
    const int cBase = blockIdx.x * 128;
    const int tid = threadIdx.x;
    const int warp = tid >> 5, lane = tid & 31;
    const int wr = warp >> 2, wc = warp & 3;

    FragC16 acc[4][2];
#pragma unroll
    for (int i = 0; i < 4; i++)
#pragma unroll
        for (int j = 0; j < 2; j++) wmma::fill_fragment(acc[i][j], 0.f);

    issue_Ah(As[0], X, mBase, 0, DD, tid);
    issue_Bh(Bs[0], g_wf1, 0, cBase, 512, tid);
    CP_COMMIT();
    int buf = 0;
    for (int kt = 0; kt < 512; kt += 32) {
        CP_WAIT0();
        __syncthreads();
        if (kt + 32 < 512) {
            int kn = kt + 32;
            const __half* Asrc = (kn < 256) ? X : At;
            int kOff = (kn < 256) ? kn : kn - 256;
            const __half* Bsrc = (kn < 256) ? g_wf1 : g_wcomb;
            int kB = (kn < 256) ? kn : kn - 256;
            issue_Ah(As[buf ^ 1], Asrc, mBase, kOff, DD, tid);
            issue_Bh(Bs[buf ^ 1], Bsrc, kB, cBase, 512, tid);
            CP_COMMIT();
        }
        gemm_core_h(As[buf], Bs[buf], acc, wr, wc);
        buf ^= 1;
    }
    __syncthreads();

    float* stg = (float*)As + warp * (16 * ST_LD);
    const int r = lane >> 1, c0 = (lane & 1) * 8;
#pragma unroll
    for (int i = 0; i < 4; i++)
#pragma unroll
        for (int j = 0; j < 2; j++) {
            wmma::store_matrix_sync(stg, acc[i][j], ST_LD, wmma::mem_row_major);
            __syncwarp();
            int gm = mBase + wr * 64 + i * 16 + r;
            int gc = cBase + wc * 32 + j * 16 + c0;
            float4 b0 = *(const float4*)(g_bcomb + gc);
            float4 b1 = *(const float4*)(g_bcomb + gc + 4);
            const float* sp = stg + r * ST_LD + c0;
            float4 v0 = make_float4(sp[0] + b0.x, sp[1] + b0.y, sp[2] + b0.z, sp[3] + b0.w);
            float4 v1 = make_float4(sp[4] + b1.x, sp[5] + b1.y, sp[6] + b1.z, sp[7] + b1.w);
            *(float4*)(&g_h[s][(size_t)gm * (2 * DD) + gc])     = v0;
            *(float4*)(&g_h[s][(size_t)gm * (2 * DD) + gc + 4]) = v1;
            __syncwarp();
        }
}

// ==========================================================================
// Kernel 5: LayerNorm(512) + exact GELU; f32 g_h -> half g_hh.
// 256 threads, 2 rows per block. grid 8192
// ==========================================================================
__global__ __launch_bounds__(256) void ln_gelu_kernel(
    const float* __restrict__ g, const float* __restrict__ bta)
{
    const int half_id = threadIdx.x >> 7;          // which row of the pair
    const int tid = threadIdx.x & 127;
    const int row = blockIdx.x * 2 + half_id;
    const int s = row >> 13;
    const int rr = row & 8191;
    const float* h = g_h[s] + (size_t)rr * 512;

    float4 t = reinterpret_cast<const float4*>(h)[tid];
    float sum = t.x + t.y + t.z + t.w;
    float sq  = t.x * t.x + t.y * t.y + t.z * t.z + t.w * t.w;
#pragma unroll
    for (int off = 16; off > 0; off >>= 1) {
        sum += __shfl_xor_sync(0xffffffffu, sum, off);
        sq  += __shfl_xor_sync(0xffffffffu, sq,  off);
    }
    __shared__ float ssum[2][4], ssq[2][4];
    const int w = tid >> 5;
    if ((tid & 31) == 0) { ssum[half_id][w] = sum; ssq[half_id][w] = sq; }
    __syncthreads();
    sum = ssum[half_id][0] + ssum[half_id][1] + ssum[half_id][2] + ssum[half_id][3];
    sq  = ssq[half_id][0]  + ssq[half_id][1]  + ssq[half_id][2]  + ssq[half_id][3];

    const float mu   = sum * (1.f / 512.f);
    const float var  = sq * (1.f / 512.f) - mu * mu;
    const float rstd = rsqrtf(var + 1e-5f);

    float4 gg = reinterpret_cast<const float4*>(g)[tid];
    float4 bb = reinterpret_cast<const float4*>(bta)[tid];
    auto act = [&](float v, float gv, float bv) {
        float y = (v - mu) * rstd * gv + bv;
        return 0.5f * y * (1.f + erff(y * 0.70710678118654752f));
    };
    float r0 = act(t.x, gg.x, bb.x);
    float r1 = act(t.y, gg.y, bb.y);
    float r2 = act(t.z, gg.z, bb.z);
    float r3 = act(t.w, gg.w, bb.w);

    __half2* dst = (__half2*)(g_hh[s] + (size_t)rr * 512 + tid * 4);
    dst[0] = __floats2half2_rn(r0, r1);
    dst[1] = __floats2half2_rn(r2, r3);
}

// ==========================================================================
// Kernel 6: FFN2 + residual.  out = x + hh @ w_f2 + b_f2 (K=512). grid (2,64,2)
// ==========================================================================
__global__ __launch_bounds__(256, 2) void ffn2_kernel(
    const float* __restrict__ x0, const float* __restrict__ x1,
    const float* __restrict__ bias, float* __restrict__ out)
{
    __shared__ __align__(16) __half As[2][128 * ASH_LD];
    __shared__ __align__(16) __half Bs[2][32 * BSH_LD];

    const int s = blockIdx.z;
    const float* X = s ? x1 : x0;
    const __half* A = g_hh[s];
    const int mBase = blockIdx.y * 128;
    const int cBase = blockIdx.x * 128;
    const int tid = threadIdx.x;
    const int warp = tid >> 5, lane = tid & 31;
    const int wr = warp >> 2, wc = warp & 3;

    FragC16 acc[4][2];
#pragma unroll
    for (int i = 0; i < 4; i++)
#pragma unroll
        for (int j = 0; j < 2; j++) wmma::fill_fragment(acc[i][j], 0.f);

    issue_Ah(As[0], A, mBase, 0, 2 * DD, tid);
    issue_Bh(Bs[0], g_wf2, 0, cBase, DD, tid);
    CP_COMMIT();
    int buf = 0;
    for (int kt = 0; kt < 512; kt += 32) {
        CP_WAIT0();
        __syncthreads();
        if (kt + 32 < 512) {
            issue_Ah(As[buf ^ 1], A, mBase, kt + 32, 2 * DD, tid);
            issue_Bh(Bs[buf ^ 1], g_wf2, kt + 32, cBase, DD, tid);
            CP_COMMIT();
        }
        gemm_core_h(As[buf], Bs[buf], acc, wr, wc);
        buf ^= 1;
    }
    __syncthreads();

    float* stg = (float*)As + warp * (16 * ST_LD);
    const int r = lane >> 1, c0 = (lane & 1) * 8;
#pragma unroll
    for (int i = 0; i < 4; i++)
#pragma unroll
        for (int j = 0; j < 2; j++) {
            wmma::store_matrix_sync(stg, acc[i][j], ST_LD, wmma::mem_row_major);
            __syncwarp();
            int gm = mBase + wr * 64 + i * 16 + r;
            int gc = cBase + wc * 32 + j * 16 + c0;
            float4 b0 = *(const float4*)(bias + gc);
            float4 b1 = *(const float4*)(bias + gc + 4);
            float4 x0v = *(const float4*)(X + (size_t)gm * DD + gc);
            float4 x1v = *(const float4*)(X + (size_t)gm * DD + gc + 4);
            const float* sp = stg + r * ST_LD + c0;
            float4 v0 = make_float4(sp[0] + b0.x + x0v.x, sp[1] + b0.y + x0v.y,
                                    sp[2] + b0.z + x0v.z, sp[3] + b0.w + x0v.w);
            float4 v1 = make_float4(sp[4] + b1.x + x1v.x, sp[5] + b1.y + x1v.y,
                                    sp[6] + b1.z + x1v.z, sp[7] + b1.w + x1v.w);
            *(float4*)(out + (size_t)s * MTOT * DD + (size_t)gm * DD + gc)     = v0;
            *(float4*)(out + (size_t)s * MTOT * DD + (size_t)gm * DD + gc + 4) = v1;
            __syncwarp();
        }
}

// ==========================================================================
extern "C" void kernel_launch(void* const* d_in, const int* in_sizes, int n_in,
                              void* d_out, int out_size)
{
    const float* x0    = (const float*)d_in[0];
    const float* x1    = (const float*)d_in[1];
    const float* w_qk  = (const float*)d_in[2];
    const float* b_qk  = (const float*)d_in[3];
    const float* w_v   = (const float*)d_in[4];
    const float* b_v   = (const float*)d_in[5];
    const float* w_out = (const float*)d_in[6];
    const float* b_out = (const float*)d_in[7];
    const float* w_f1  = (const float*)d_in[8];
    const float* b_f1  = (const float*)d_in[9];
    const float* ln_g  = (const float*)d_in[10];
    const float* ln_b  = (const float*)d_in[11];
    const float* w_f2  = (const float*)d_in[12];
    const float* b_f2  = (const float*)d_in[13];
    float* out = (float*)d_out;

    cudaFuncSetAttribute(attn_kernel,
                         cudaFuncAttributeMaxDynamicSharedMemorySize, ATTN_SMEM);

    cvt_kernel    <<<dim3(2048, 7), 256>>>(x0, x1, w_qk, w_v, w_out, w_f1, w_f2);
    bcomb_kernel  <<<4, 128>>>(b_out, w_f1, b_f1);
    wcomb_kernel  <<<dim3(4, 2), 256>>>();
    qkv_kernel    <<<dim3(4, 64, 2), 256>>>(b_qk, b_v);
    attn_kernel   <<<dim3(16, 16, 2), 256, ATTN_SMEM>>>();
    ffn1_kernel   <<<dim3(4, 64, 2), 256>>>();
    ln_gelu_kernel<<<8192, 256>>>(ln_g, ln_b);
    ffn2_kernel   <<<dim3(2, 64, 2), 256>>>(x0, x1, b_f2, out);
}